// round 16
// baseline (speedup 1.0000x reference)
#include <cuda_runtime.h>
#include <cuda_fp16.h>
#include <math.h>
#include <stdint.h>

// ---------------------------------------------------------------------------
// GPNN_VCOCO forward — fp16 split GEMMs on warp-level mma.sync.
// R16: un-fuse M+T1 — profile showed the generic GEMM runs 0.168 us/unit
// (400 TF/s, no spills, 2 CTAs/SM) vs the fused kernel's 0.244 (254 regs,
// spilling). conv_act reinstated; M = MFUSE epilogue, T1 = RELU, both on
// the generic kernel. Hn 1-plane; all weight conversions hi-only.
// ---------------------------------------------------------------------------

namespace {

constexpr int Bb = 16;
constexpr int Nn = 64;
constexpr int Cc = 512;
constexpr int Rr = Bb * Nn * Nn;   // 65536

// ---------------- scratch (static device globals) ----------------
__device__ __half g_EFh[Rr * Cc];
__device__ __half g_Mh [Rr * Cc];
__device__ __half g_Th [Rr * Cc];
__device__ __half g_Wmh [Cc * Cc];                 // Wm edge half, hi
__device__ __half g_WmNh[Cc * Cc];                 // Wm node half, hi
__device__ __half g_W1h [Cc * Cc];
__device__ __half g_W2h [Cc * Cc];
__device__ __half g_Wihh[3 * Cc * Cc];
__device__ __half g_Whhh[3 * Cc * Cc];
__device__ __half g_NFh [Bb * Nn * Cc];
__device__ __half g_msh [Bb * Nn * Cc];
__device__ float g_Hn [Bb * Nn * Cc];
__device__ float g_pa1[Rr];
__device__ float g_GI [Bb * Nn * 3 * Cc];
__device__ float g_GH [Bb * Nn * 3 * Cc];

__device__ __forceinline__ float sigmoidf_(float x) {
    return 1.0f / (1.0f + __expf(-x));
}
__device__ __forceinline__ int permrow(int gr) {
    return (gr & ~4095) | ((gr & 63) << 6) | ((gr >> 6) & 63);
}
__device__ __forceinline__ uint32_t smem_u32(const void* p) {
    uint32_t a;
    asm("{ .reg .u64 t; cvta.to.shared.u64 t, %1; cvt.u32.u64 %0, t; }"
        : "=r"(a) : "l"(p));
    return a;
}
__device__ __forceinline__ uint32_t swz(uint32_t o) {   // 128B-row xor swizzle
    return o ^ ((o >> 3) & 0x70);
}
__device__ __forceinline__ void cp16(uint32_t saddr, const void* g) {
    asm volatile("cp.async.cg.shared.global [%0], [%1], 16;"
                 :: "r"(saddr), "l"(g) : "memory");
}
__device__ __forceinline__ void cp_commit() {
    asm volatile("cp.async.commit_group;" ::: "memory");
}
template<int N>
__device__ __forceinline__ void cp_wait() {
    asm volatile("cp.async.wait_group %0;" :: "n"(N) : "memory");
}
__device__ __forceinline__ void ldm_x4(uint32_t* r, uint32_t addr) {
    asm volatile("ldmatrix.sync.aligned.m8n8.x4.shared.b16 {%0,%1,%2,%3}, [%4];"
                 : "=r"(r[0]), "=r"(r[1]), "=r"(r[2]), "=r"(r[3]) : "r"(addr));
}
__device__ __forceinline__ void mma16816(float* c, const uint32_t* a,
                                         uint32_t b0, uint32_t b1) {
    asm volatile(
        "mma.sync.aligned.m16n8k16.row.col.f32.f16.f16.f32 "
        "{%0,%1,%2,%3}, {%4,%5,%6,%7}, {%8,%9}, {%0,%1,%2,%3};"
        : "+f"(c[0]), "+f"(c[1]), "+f"(c[2]), "+f"(c[3])
        : "r"(a[0]), "r"(a[1]), "r"(a[2]), "r"(a[3]), "r"(b0), "r"(b1));
}

enum { TEPI_MFUSE = 0, TEPI_RELU = 1, TEPI_DOT = 2, TEPI_BIAS = 3 };

constexpr int STAGE_BYTES = 32768;           // 16KB A + 16KB B
constexpr int SMEM_BYTES  = 3 * STAGE_BYTES; // 96KB -> 2 CTAs/SM

// ---------------------------------------------------------------------------
// Generic HMMA GEMM: CTA 128x128, 128 thr, warp 64x64, 3-stage cp.async.
// Dual mode via blockIdx.z for GI+GH. PLANES: 1 = Ah*Bh; 2 = +Al*Bh;
// 3 = +Ah*Bl. Epilogues: MFUSE (relu + Hn row), RELU (relu + bias, opt PERM
// sigmoid row scale), DOT (relu+bias dot Wlo -> atomic), BIAS (fp32 + bias).
// ---------------------------------------------------------------------------
template<int EPI, bool PERM, int PLANES>
__global__ void __launch_bounds__(128, 2)
hmma_gemm(const __half* AhP, const __half* AlP,
          const __half* BhP, const __half* BlP,
          const float* biasP,
          const float* extra,               // Wlo (DOT) | Hn (MFUSE)
          const float* pa,                  // pa1 logits (PERM)
          __half* Ch,                       // fp16 out (RELU/MFUSE)
          float* CfP, int ldC,              // fp32 out (BIAS)
          float* dotOut,                    // atomic target (DOT)
          const __half* A2h, const __half* A2l,
          const __half* B2h, const __half* B2l,
          const float* bias2, float* Cf2)
{
    extern __shared__ __align__(128) uint8_t smem[];
    const uint32_t sBase = smem_u32(smem);
    constexpr int NCHUNK = PLANES * 8;

    const bool sec = (blockIdx.z == 1);
    const __half* Ah = sec ? A2h : AhP;
    const __half* Al = sec ? A2l : AlP;
    const __half* Bh = sec ? B2h : BhP;
    const __half* Bl = sec ? B2l : BlP;
    const float* bias = sec ? bias2 : biasP;
    float* Cf = sec ? Cf2 : CfP;

    const int tid = threadIdx.x;
    const int wid = tid >> 5, lane = tid & 31;
    const int warp_m = wid & 1, warp_n = wid >> 1;
    const int rowBase = blockIdx.y << 7;
    const int colBase = blockIdx.x << 7;

    const int lrow = tid >> 3, lseg = tid & 7;
    uint32_t aOff[8], bOff[8], sOff[8];
#pragma unroll
    for (int i = 0; i < 8; i++) {
        const int row = lrow + i * 16;
        int sr = rowBase + row;
        if (PERM) sr = permrow(sr);
        aOff[i] = (uint32_t)sr * 512u + lseg * 8;
        bOff[i] = (uint32_t)(colBase + row) * 512u + lseg * 8;
        sOff[i] = swz((uint32_t)row * 128 + lseg * 16);
    }

    auto load_stage = [&](int st, int ch) {
        const int p  = ch >> 3;
        const int kb = (ch & 7) * 64;
        const __half* Ap = (p == 1) ? Al : Ah;
        const __half* Bp = (p == 2) ? Bl : Bh;
        const uint32_t sa = sBase + st * STAGE_BYTES;
        const uint32_t sb = sa + 16384;
#pragma unroll
        for (int i = 0; i < 8; i++) {
            cp16(sa + sOff[i], Ap + aOff[i] + kb);
            cp16(sb + sOff[i], Bp + bOff[i] + kb);
        }
        cp_commit();
    };

    load_stage(0, 0);
    load_stage(1, 1);

    float acc[4][8][4];
#pragma unroll
    for (int mt = 0; mt < 4; mt++)
#pragma unroll
        for (int nf = 0; nf < 8; nf++)
#pragma unroll
            for (int j = 0; j < 4; j++) acc[mt][nf][j] = 0.0f;

    const int aRow = warp_m * 64 + ((lane >> 3) & 1) * 8 + (lane & 7);
    const uint32_t aK = (uint32_t)(lane >> 4) * 16;
    const int bRow = warp_n * 64 + (lane >> 4) * 8 + (lane & 7);
    const uint32_t bK = (uint32_t)((lane >> 3) & 1) * 16;

#pragma unroll 1
    for (int ch = 0; ch < NCHUNK; ch++) {
        if (ch < NCHUNK - 1) cp_wait<1>(); else cp_wait<0>();
        __syncthreads();
        if (ch + 2 < NCHUNK) load_stage((ch + 2) % 3, ch + 2);

        const uint32_t sa = sBase + (ch % 3) * STAGE_BYTES;
        const uint32_t sb = sa + 16384;
#pragma unroll
        for (int ks = 0; ks < 4; ks++) {
            uint32_t a[4][4], b[4][4];
#pragma unroll
            for (int mt = 0; mt < 4; mt++)
                ldm_x4(a[mt], sa + swz((uint32_t)(aRow + mt * 16) * 128 + ks * 32 + aK));
#pragma unroll
            for (int pr = 0; pr < 4; pr++)
                ldm_x4(b[pr], sb + swz((uint32_t)(bRow + pr * 16) * 128 + ks * 32 + bK));
#pragma unroll
            for (int mt = 0; mt < 4; mt++)
#pragma unroll
                for (int nf = 0; nf < 8; nf++)
                    mma16816(acc[mt][nf], a[mt],
                             b[nf >> 1][(nf & 1) * 2], b[nf >> 1][(nf & 1) * 2 + 1]);
        }
    }

    const int r0 = rowBase + warp_m * 64 + (lane >> 2);
    const int c0 = colBase + warp_n * 64 + (lane & 3) * 2;

    if (EPI == TEPI_DOT) {
        float dsum[4][2];
#pragma unroll
        for (int mt = 0; mt < 4; mt++) { dsum[mt][0] = 0.f; dsum[mt][1] = 0.f; }
#pragma unroll
        for (int mt = 0; mt < 4; mt++)
#pragma unroll
            for (int nf = 0; nf < 8; nf++) {
                const int gc = c0 + nf * 8;
                const float b0v = bias[gc], b1v = bias[gc + 1];
                const float w0v = extra[gc], w1v = extra[gc + 1];
                dsum[mt][0] += fmaxf(acc[mt][nf][0] + b0v, 0.f) * w0v
                             + fmaxf(acc[mt][nf][1] + b1v, 0.f) * w1v;
                dsum[mt][1] += fmaxf(acc[mt][nf][2] + b0v, 0.f) * w0v
                             + fmaxf(acc[mt][nf][3] + b1v, 0.f) * w1v;
            }
#pragma unroll
        for (int mt = 0; mt < 4; mt++)
#pragma unroll
            for (int h = 0; h < 2; h++) {
                float v = dsum[mt][h];
                v += __shfl_xor_sync(0xffffffffu, v, 1);
                v += __shfl_xor_sync(0xffffffffu, v, 2);
                if ((lane & 3) == 0)
                    atomicAdd(dotOut + r0 + mt * 16 + h * 8, v);
            }
    } else if (EPI == TEPI_BIAS) {
#pragma unroll
        for (int mt = 0; mt < 4; mt++)
#pragma unroll
            for (int h = 0; h < 2; h++) {
                const int row = r0 + mt * 16 + h * 8;
                float2* orow = reinterpret_cast<float2*>(Cf + (size_t)row * ldC);
#pragma unroll
                for (int nf = 0; nf < 8; nf++) {
                    const int gc = c0 + nf * 8;
                    orow[gc >> 1] = make_float2(acc[mt][nf][h * 2] + bias[gc],
                                                acc[mt][nf][h * 2 + 1] + bias[gc + 1]);
                }
            }
    } else {   // RELU (opt PERM row scale) or MFUSE (+Hn row)
#pragma unroll
        for (int mt = 0; mt < 4; mt++)
#pragma unroll
            for (int h = 0; h < 2; h++) {
                const int row = r0 + mt * 16 + h * 8;
                float s = 1.0f;
                if (PERM) s = sigmoidf_(pa[permrow(row)]);
                const float* hnrow = nullptr;
                if (EPI == TEPI_MFUSE)
                    hnrow = extra + (size_t)(((row >> 12) << 6) | (row & 63)) * 512;
                uint32_t* oh = reinterpret_cast<uint32_t*>(Ch) + ((size_t)row * 512 >> 1);
#pragma unroll
                for (int nf = 0; nf < 8; nf++) {
                    const int gc = c0 + nf * 8;
                    float y0, y1;
                    if (EPI == TEPI_MFUSE) {
                        y0 = fmaxf(acc[mt][nf][h * 2]     + hnrow[gc],     0.0f);
                        y1 = fmaxf(acc[mt][nf][h * 2 + 1] + hnrow[gc + 1], 0.0f);
                    } else {
                        y0 = fmaxf(fmaf(s, acc[mt][nf][h * 2],     bias[gc]),     0.0f);
                        y1 = fmaxf(fmaf(s, acc[mt][nf][h * 2 + 1], bias[gc + 1]), 0.0f);
                    }
                    __half2 h2;
                    h2.x = __float2half_rn(y0);
                    h2.y = __float2half_rn(y1);
                    oh[gc >> 1] = *reinterpret_cast<uint32_t*>(&h2);
                }
            }
    }
}

// ---------------------------------------------------------------------------
// conversions
// ---------------------------------------------------------------------------
// plain fp32 -> fp16 cast (hi plane only), vectorized — EF
__global__ void conv_act(const float4* __restrict__ in,
                         uint2* __restrict__ hi, int n4)
{
    const int i = blockIdx.x * blockDim.x + threadIdx.x;
    if (i >= n4) return;
    const float4 v = in[i];
    __half2 hA, hB;
    hA.x = __float2half_rn(v.x); hA.y = __float2half_rn(v.y);
    hB.x = __float2half_rn(v.z); hB.y = __float2half_rn(v.w);
    hi[i] = make_uint2(*reinterpret_cast<uint32_t*>(&hA), *reinterpret_cast<uint32_t*>(&hB));
}

// Weight conversions (hi-only) + NF cast + pa-accumulator init, one launch.
// Segments (S = 256K elements):
//   [0,S)     Wm edge -> Wmh       [S,2S)   Wm node -> WmNh
//   [2S,3S)   Wl1 -> W1h           [3S,4S)  Wl2 -> W2h
//   [4S,7S)   Wih -> Wihh          [7S,10S) Whh -> Whhh
//   [10S,12S) NF -> NFh
//   [12S,12S+16384) pa1/out float4 fill with blo
__global__ void conv_weights(const float* __restrict__ Wm,
                             const float* __restrict__ Wl1,
                             const float* __restrict__ Wl2,
                             const float* __restrict__ Wih,
                             const float* __restrict__ Whh,
                             const float* __restrict__ NF,
                             __half* __restrict__ Wmh,  __half* __restrict__ WmNh,
                             __half* __restrict__ W1h,  __half* __restrict__ W2h,
                             __half* __restrict__ Wihh, __half* __restrict__ Whhh,
                             __half* __restrict__ NFh,
                             const float* __restrict__ blo,
                             float4* __restrict__ pa1, float4* __restrict__ pa2)
{
    const int idx = blockIdx.x * blockDim.x + threadIdx.x;
    constexpr int S = 512 * 512;
    if (idx >= 12 * S) {
        const int o = idx - 12 * S;
        if (o < Rr / 4) {
            const float v = blo[0];
            const float4 f = make_float4(v, v, v, v);
            pa1[o] = f;
            pa2[o] = f;
        }
        return;
    }
    float x;
    __half* hi;
    int off;
    if (idx < S) {
        off = idx;
        x = Wm[(size_t)(off >> 9) * 1024 + 512 + (off & 511)];
        hi = Wmh + off;
    } else if (idx < 2 * S) {
        off = idx - S;
        x = Wm[(size_t)(off >> 9) * 1024 + (off & 511)];
        hi = WmNh + off;
    } else if (idx < 3 * S) {
        off = idx - 2 * S;
        x = Wl1[off];
        hi = W1h + off;
    } else if (idx < 4 * S) {
        off = idx - 3 * S;
        x = Wl2[off];
        hi = W2h + off;
    } else if (idx < 7 * S) {
        off = idx - 4 * S;
        x = Wih[off];
        hi = Wihh + off;
    } else if (idx < 10 * S) {
        off = idx - 7 * S;
        x = Whh[off];
        hi = Whhh + off;
    } else {
        off = idx - 10 * S;
        x = NF[off];
        hi = NFh + off;
    }
    *hi = __float2half_rn(x);
}

// msum[b,v,:] = sum_w sig(pa2[b,v,w]) * Mh[(b,v,w), :]  -> fp16 hi only
__global__ void msum2(const __half* __restrict__ Mh,
                      const float* __restrict__ pa2,
                      __half* __restrict__ msh)
{
    const int bv = blockIdx.x;
    const int t  = threadIdx.x;   // 128
    __shared__ float sg[64];
    if (t < 64) sg[t] = sigmoidf_(pa2[bv * 64 + t]);
    __syncthreads();
    const uint32_t* mh = reinterpret_cast<const uint32_t*>(Mh + (size_t)bv * 64 * 512);
    const int c = t * 2;
    float a0 = 0.f, a1 = 0.f, a2 = 0.f, a3 = 0.f;
#pragma unroll 4
    for (int w = 0; w < 64; w++) {
        const float s = sg[w];
        const uint32_t h0 = mh[w * 256 + c];
        const uint32_t h1 = mh[w * 256 + c + 1];
        const __half2 H0 = *reinterpret_cast<const __half2*>(&h0);
        const __half2 H1 = *reinterpret_cast<const __half2*>(&h1);
        a0 = fmaf(s, __half2float(H0.x), a0);
        a1 = fmaf(s, __half2float(H0.y), a1);
        a2 = fmaf(s, __half2float(H1.x), a2);
        a3 = fmaf(s, __half2float(H1.y), a3);
    }
    __half2 h2a, h2b;
    h2a.x = __float2half_rn(a0); h2a.y = __float2half_rn(a1);
    h2b.x = __float2half_rn(a2); h2b.y = __float2half_rn(a3);
    uint2* oh = reinterpret_cast<uint2*>(msh + (size_t)bv * 512) + t;
    *oh = make_uint2(*reinterpret_cast<uint32_t*>(&h2a), *reinterpret_cast<uint32_t*>(&h2b));
}

__global__ void gru_readout(const float* __restrict__ GI,
                            const float* __restrict__ GH,
                            const float* __restrict__ NF,
                            const float* __restrict__ Wr1, const float* __restrict__ br1,
                            const float* __restrict__ Wr2, const float* __restrict__ br2,
                            float* __restrict__ out)
{
    const int row = blockIdx.x;
    __shared__ float hn[512];
    const int t = threadIdx.x;   // 256
    const float* gi = GI + (size_t)row * 1536;
    const float* gh = GH + (size_t)row * 1536;
    const float* h  = NF + (size_t)row * 512;
    for (int d = t; d < 512; d += 256) {
        const float r = sigmoidf_(gi[d] + gh[d]);
        const float z = sigmoidf_(gi[512 + d] + gh[512 + d]);
        const float n = tanhf(gi[1024 + d] + r * gh[1024 + d]);
        hn[d] = (1.0f - z) * n + z * h[d];
    }
    __syncthreads();
    const int warp = t >> 5, lane = t & 31;
    for (int o = warp; o < 28; o += 8) {
        const float* Wr = (o < 26) ? (Wr1 + o * 512) : (Wr2 + (o - 26) * 512);
        float acc = 0.0f;
        for (int k = lane; k < 512; k += 32) acc = fmaf(hn[k], Wr[k], acc);
#pragma unroll
        for (int off = 16; off; off >>= 1)
            acc += __shfl_down_sync(0xffffffffu, acc, off);
        if (lane == 0) {
            if (o < 26) out[65536 + row * 26 + o]               = acc + br1[o];
            else        out[65536 + 26624 + row * 2 + (o - 26)] = acc + br2[o - 26];
        }
    }
}

} // namespace

extern "C" void kernel_launch(void* const* d_in, const int* /*in_sizes*/, int /*n_in*/,
                              void* d_out, int /*out_size*/)
{
    const float* EF  = (const float*)d_in[0];
    const float* NF  = (const float*)d_in[1];
    const float* Wm  = (const float*)d_in[4];
    const float* bm  = (const float*)d_in[5];
    const float* Wl1 = (const float*)d_in[6];
    const float* bl1 = (const float*)d_in[7];
    const float* Wl2 = (const float*)d_in[8];
    const float* bl2 = (const float*)d_in[9];
    const float* Wlo = (const float*)d_in[10];
    const float* blo = (const float*)d_in[11];
    const float* Wih = (const float*)d_in[12];
    const float* bih = (const float*)d_in[13];
    const float* Whh = (const float*)d_in[14];
    const float* bhh = (const float*)d_in[15];
    const float* Wr1 = (const float*)d_in[16];
    const float* br1 = (const float*)d_in[17];
    const float* Wr2 = (const float*)d_in[18];
    const float* br2 = (const float*)d_in[19];
    float* out = (float*)d_out;

    __half *pEFh, *pMh, *pTh;
    __half *pWmh, *pWmNh, *pW1h, *pW2h;
    __half *pWihh, *pWhhh, *pNFh, *pmsh;
    float *pHn, *pPa1, *pGI, *pGH;
    cudaGetSymbolAddress((void**)&pEFh,  g_EFh);
    cudaGetSymbolAddress((void**)&pMh,   g_Mh);
    cudaGetSymbolAddress((void**)&pTh,   g_Th);
    cudaGetSymbolAddress((void**)&pWmh,  g_Wmh);
    cudaGetSymbolAddress((void**)&pWmNh, g_WmNh);
    cudaGetSymbolAddress((void**)&pW1h,  g_W1h);
    cudaGetSymbolAddress((void**)&pW2h,  g_W2h);
    cudaGetSymbolAddress((void**)&pWihh, g_Wihh);
    cudaGetSymbolAddress((void**)&pWhhh, g_Whhh);
    cudaGetSymbolAddress((void**)&pNFh,  g_NFh);
    cudaGetSymbolAddress((void**)&pmsh,  g_msh);
    cudaGetSymbolAddress((void**)&pHn,   g_Hn);
    cudaGetSymbolAddress((void**)&pPa1,  g_pa1);
    cudaGetSymbolAddress((void**)&pGI,   g_GI);
    cudaGetSymbolAddress((void**)&pGH,   g_GH);

    auto kBIAS1 = hmma_gemm<TEPI_BIAS,  false, 1>;  // Hn, GI, GH (1-plane)
    auto kMF    = hmma_gemm<TEPI_MFUSE, false, 1>;  // M
    auto kRE    = hmma_gemm<TEPI_RELU,  false, 1>;  // T1
    auto kRP    = hmma_gemm<TEPI_RELU,  true,  1>;  // T1' (perm + sigmoid)
    auto kDOT   = hmma_gemm<TEPI_DOT,   false, 1>;
    cudaFuncSetAttribute(kBIAS1, cudaFuncAttributeMaxDynamicSharedMemorySize, SMEM_BYTES);
    cudaFuncSetAttribute(kMF,    cudaFuncAttributeMaxDynamicSharedMemorySize, SMEM_BYTES);
    cudaFuncSetAttribute(kRE,    cudaFuncAttributeMaxDynamicSharedMemorySize, SMEM_BYTES);
    cudaFuncSetAttribute(kRP,    cudaFuncAttributeMaxDynamicSharedMemorySize, SMEM_BYTES);
    cudaFuncSetAttribute(kDOT,   cudaFuncAttributeMaxDynamicSharedMemorySize, SMEM_BYTES);

    // conversions: EF cast (vectorized) + weights/NF/pa init
    const int n4ef = Rr * Cc / 4;
    conv_act<<<(n4ef + 255) / 256, 256>>>((const float4*)EF, (uint2*)pEFh, n4ef);
    conv_weights<<<12352, 256>>>(Wm, Wl1, Wl2, Wih, Whh, NF,
                                 pWmh, pWmNh, pW1h, pW2h,
                                 pWihh, pWhhh, pNFh,
                                 blo, (float4*)pPa1, (float4*)out);

    // Hn = NF @ Wm[:, :512]^T + bm   (1-plane; feeds fp16-rounded M)
    kBIAS1<<<dim3(4, 8, 1), 128, SMEM_BYTES>>>(pNFh, nullptr, pWmNh, nullptr, bm,
                                               nullptr, nullptr, nullptr,
                                               pHn, 512, nullptr,
                                               nullptr, nullptr, nullptr, nullptr,
                                               nullptr, nullptr);

    const dim3 gTC(4, 512, 1);
    // M = relu(EF @ WmE^T + Hn) -> Mh
    kMF<<<gTC, 128, SMEM_BYTES>>>(pEFh, nullptr, pWmh, nullptr, nullptr, pHn,
                                  nullptr, pMh, nullptr, 0, nullptr,
                                  nullptr, nullptr, nullptr, nullptr,
                                  nullptr, nullptr);
    // T1 = relu(EF @ Wl1^T + bl1) -> Th
    kRE<<<gTC, 128, SMEM_BYTES>>>(pEFh, nullptr, pW1h, nullptr, bl1, nullptr,
                                  nullptr, pTh, nullptr, 0, nullptr,
                                  nullptr, nullptr, nullptr, nullptr,
                                  nullptr, nullptr);
    // pa1 += dot(relu(T1 @ Wl2^T + bl2), Wlo)
    kDOT<<<gTC, 128, SMEM_BYTES>>>(pTh, nullptr, pW2h, nullptr, bl2, Wlo,
                                   nullptr, nullptr, nullptr, 0, pPa1,
                                   nullptr, nullptr, nullptr, nullptr,
                                   nullptr, nullptr);
    // T1' = relu(sig(pa1[perm]) * M[perm] @ Wl1^T + bl1) -> Th
    kRP<<<gTC, 128, SMEM_BYTES>>>(pMh, nullptr, pW1h, nullptr, bl1, nullptr,
                                  pPa1, pTh, nullptr, 0, nullptr,
                                  nullptr, nullptr, nullptr, nullptr,
                                  nullptr, nullptr);
    // pred_adj += dot(relu(T1' @ Wl2^T + bl2), Wlo)
    kDOT<<<gTC, 128, SMEM_BYTES>>>(pTh, nullptr, pW2h, nullptr, bl2, Wlo,
                                   nullptr, nullptr, nullptr, 0, out,
                                   nullptr, nullptr, nullptr, nullptr,
                                   nullptr, nullptr);

    msum2<<<Bb * Nn, 128>>>(pMh, out, pmsh);
    // GI and GH in one dual launch (1-plane: Ah*Bh)
    kBIAS1<<<dim3(12, 8, 2), 128, SMEM_BYTES>>>(pmsh, nullptr, pWihh, nullptr, bih,
                                                nullptr, nullptr, nullptr,
                                                pGI, 1536, nullptr,
                                                pNFh, nullptr, pWhhh, nullptr,
                                                bhh, pGH);
    gru_readout<<<Bb * Nn, 256>>>(pGI, pGH, NF, Wr1, br1, Wr2, br2, out);
}

// round 17
// speedup vs baseline: 1.1483x; 1.1483x over previous
#include <cuda_runtime.h>
#include <cuda_fp16.h>
#include <math.h>
#include <stdint.h>

// ---------------------------------------------------------------------------
// GPNN_VCOCO forward — fp16 split GEMMs on warp-level mma.sync.
// R17: R15 structure + the Hn epilogue gather (diagnosed at ~80-90 us of
// 32B-sector L2 traffic) replaced by a coalesced smem-staged Hn tile in the
// fused M+T1 kernel. Hn GEMM 1-plane; all conversions hi-only.
// ---------------------------------------------------------------------------

namespace {

constexpr int Bb = 16;
constexpr int Nn = 64;
constexpr int Cc = 512;
constexpr int Rr = Bb * Nn * Nn;   // 65536

// ---------------- scratch (static device globals) ----------------
__device__ __half g_Mh [Rr * Cc];
__device__ __half g_Th [Rr * Cc];
__device__ __half g_Wmh [Cc * Cc];                 // Wm edge half, hi
__device__ __half g_WmNh[Cc * Cc];                 // Wm node half, hi
__device__ __half g_W1h [Cc * Cc];
__device__ __half g_W2h [Cc * Cc];
__device__ __half g_Wihh[3 * Cc * Cc];
__device__ __half g_Whhh[3 * Cc * Cc];
__device__ __half g_NFh [Bb * Nn * Cc];
__device__ __half g_msh [Bb * Nn * Cc];
__device__ float g_Hn [Bb * Nn * Cc];
__device__ float g_pa1[Rr];
__device__ float g_GI [Bb * Nn * 3 * Cc];
__device__ float g_GH [Bb * Nn * 3 * Cc];

__device__ __forceinline__ float sigmoidf_(float x) {
    return 1.0f / (1.0f + __expf(-x));
}
__device__ __forceinline__ int permrow(int gr) {
    return (gr & ~4095) | ((gr & 63) << 6) | ((gr >> 6) & 63);
}
__device__ __forceinline__ uint32_t smem_u32(const void* p) {
    uint32_t a;
    asm("{ .reg .u64 t; cvta.to.shared.u64 t, %1; cvt.u32.u64 %0, t; }"
        : "=r"(a) : "l"(p));
    return a;
}
__device__ __forceinline__ uint32_t swz(uint32_t o) {   // 128B-row xor swizzle
    return o ^ ((o >> 3) & 0x70);
}
__device__ __forceinline__ void cp16(uint32_t saddr, const void* g) {
    asm volatile("cp.async.cg.shared.global [%0], [%1], 16;"
                 :: "r"(saddr), "l"(g) : "memory");
}
__device__ __forceinline__ void cp_commit() {
    asm volatile("cp.async.commit_group;" ::: "memory");
}
template<int N>
__device__ __forceinline__ void cp_wait() {
    asm volatile("cp.async.wait_group %0;" :: "n"(N) : "memory");
}
__device__ __forceinline__ void ldm_x4(uint32_t* r, uint32_t addr) {
    asm volatile("ldmatrix.sync.aligned.m8n8.x4.shared.b16 {%0,%1,%2,%3}, [%4];"
                 : "=r"(r[0]), "=r"(r[1]), "=r"(r[2]), "=r"(r[3]) : "r"(addr));
}
__device__ __forceinline__ void mma16816(float* c, const uint32_t* a,
                                         uint32_t b0, uint32_t b1) {
    asm volatile(
        "mma.sync.aligned.m16n8k16.row.col.f32.f16.f16.f32 "
        "{%0,%1,%2,%3}, {%4,%5,%6,%7}, {%8,%9}, {%0,%1,%2,%3};"
        : "+f"(c[0]), "+f"(c[1]), "+f"(c[2]), "+f"(c[3])
        : "r"(a[0]), "r"(a[1]), "r"(a[2]), "r"(a[3]), "r"(b0), "r"(b1));
}

enum { TEPI_MFUSE = 0, TEPI_RELU = 1, TEPI_DOT = 2, TEPI_BIAS = 3 };

constexpr int STAGE_BYTES = 32768;           // 16KB A + 16KB B
constexpr int SMEM_BYTES  = 3 * STAGE_BYTES; // 96KB -> 2 CTAs/SM

// ---------------------------------------------------------------------------
// Generic HMMA GEMM (R11-exact): CTA 128x128, 128 thr, warp 64x64, 3-stage
// cp.async. Dual mode via blockIdx.z for GI+GH. PLANES: 1/2/3.
// ---------------------------------------------------------------------------
template<int EPI, bool PERM, int PLANES>
__global__ void __launch_bounds__(128, 2)
hmma_gemm(const __half* AhP, const __half* AlP,
          const __half* BhP, const __half* BlP,
          const float* biasP,
          const float* extra,               // Wlo (DOT)
          const float* pa,                  // pa1 logits (PERM)
          __half* Ch,                       // fp16 out (RELU)
          float* CfP, int ldC,              // fp32 out (BIAS)
          float* dotOut,                    // atomic target (DOT)
          const __half* A2h, const __half* A2l,
          const __half* B2h, const __half* B2l,
          const float* bias2, float* Cf2)
{
    extern __shared__ __align__(128) uint8_t smem[];
    const uint32_t sBase = smem_u32(smem);
    constexpr int NCHUNK = PLANES * 8;

    const bool sec = (blockIdx.z == 1);
    const __half* Ah = sec ? A2h : AhP;
    const __half* Al = sec ? A2l : AlP;
    const __half* Bh = sec ? B2h : BhP;
    const __half* Bl = sec ? B2l : BlP;
    const float* bias = sec ? bias2 : biasP;
    float* Cf = sec ? Cf2 : CfP;

    const int tid = threadIdx.x;
    const int wid = tid >> 5, lane = tid & 31;
    const int warp_m = wid & 1, warp_n = wid >> 1;
    const int rowBase = blockIdx.y << 7;
    const int colBase = blockIdx.x << 7;

    const int lrow = tid >> 3, lseg = tid & 7;
    uint32_t aOff[8], bOff[8], sOff[8];
#pragma unroll
    for (int i = 0; i < 8; i++) {
        const int row = lrow + i * 16;
        int sr = rowBase + row;
        if (PERM) sr = permrow(sr);
        aOff[i] = (uint32_t)sr * 512u + lseg * 8;
        bOff[i] = (uint32_t)(colBase + row) * 512u + lseg * 8;
        sOff[i] = swz((uint32_t)row * 128 + lseg * 16);
    }

    auto load_stage = [&](int st, int ch) {
        const int p  = ch >> 3;
        const int kb = (ch & 7) * 64;
        const __half* Ap = (p == 1) ? Al : Ah;
        const __half* Bp = (p == 2) ? Bl : Bh;
        const uint32_t sa = sBase + st * STAGE_BYTES;
        const uint32_t sb = sa + 16384;
#pragma unroll
        for (int i = 0; i < 8; i++) {
            cp16(sa + sOff[i], Ap + aOff[i] + kb);
            cp16(sb + sOff[i], Bp + bOff[i] + kb);
        }
        cp_commit();
    };

    load_stage(0, 0);
    load_stage(1, 1);

    float acc[4][8][4];
#pragma unroll
    for (int mt = 0; mt < 4; mt++)
#pragma unroll
        for (int nf = 0; nf < 8; nf++)
#pragma unroll
            for (int j = 0; j < 4; j++) acc[mt][nf][j] = 0.0f;

    const int aRow = warp_m * 64 + ((lane >> 3) & 1) * 8 + (lane & 7);
    const uint32_t aK = (uint32_t)(lane >> 4) * 16;
    const int bRow = warp_n * 64 + (lane >> 4) * 8 + (lane & 7);
    const uint32_t bK = (uint32_t)((lane >> 3) & 1) * 16;

#pragma unroll 1
    for (int ch = 0; ch < NCHUNK; ch++) {
        if (ch < NCHUNK - 1) cp_wait<1>(); else cp_wait<0>();
        __syncthreads();
        if (ch + 2 < NCHUNK) load_stage((ch + 2) % 3, ch + 2);

        const uint32_t sa = sBase + (ch % 3) * STAGE_BYTES;
        const uint32_t sb = sa + 16384;
#pragma unroll
        for (int ks = 0; ks < 4; ks++) {
            uint32_t a[4][4], b[4][4];
#pragma unroll
            for (int mt = 0; mt < 4; mt++)
                ldm_x4(a[mt], sa + swz((uint32_t)(aRow + mt * 16) * 128 + ks * 32 + aK));
#pragma unroll
            for (int pr = 0; pr < 4; pr++)
                ldm_x4(b[pr], sb + swz((uint32_t)(bRow + pr * 16) * 128 + ks * 32 + bK));
#pragma unroll
            for (int mt = 0; mt < 4; mt++)
#pragma unroll
                for (int nf = 0; nf < 8; nf++)
                    mma16816(acc[mt][nf], a[mt],
                             b[nf >> 1][(nf & 1) * 2], b[nf >> 1][(nf & 1) * 2 + 1]);
        }
    }

    const int r0 = rowBase + warp_m * 64 + (lane >> 2);
    const int c0 = colBase + warp_n * 64 + (lane & 3) * 2;

    if (EPI == TEPI_DOT) {
        float dsum[4][2];
#pragma unroll
        for (int mt = 0; mt < 4; mt++) { dsum[mt][0] = 0.f; dsum[mt][1] = 0.f; }
#pragma unroll
        for (int mt = 0; mt < 4; mt++)
#pragma unroll
            for (int nf = 0; nf < 8; nf++) {
                const int gc = c0 + nf * 8;
                const float b0v = bias[gc], b1v = bias[gc + 1];
                const float w0v = extra[gc], w1v = extra[gc + 1];
                dsum[mt][0] += fmaxf(acc[mt][nf][0] + b0v, 0.f) * w0v
                             + fmaxf(acc[mt][nf][1] + b1v, 0.f) * w1v;
                dsum[mt][1] += fmaxf(acc[mt][nf][2] + b0v, 0.f) * w0v
                             + fmaxf(acc[mt][nf][3] + b1v, 0.f) * w1v;
            }
#pragma unroll
        for (int mt = 0; mt < 4; mt++)
#pragma unroll
            for (int h = 0; h < 2; h++) {
                float v = dsum[mt][h];
                v += __shfl_xor_sync(0xffffffffu, v, 1);
                v += __shfl_xor_sync(0xffffffffu, v, 2);
                if ((lane & 3) == 0)
                    atomicAdd(dotOut + r0 + mt * 16 + h * 8, v);
            }
    } else if (EPI == TEPI_BIAS) {
#pragma unroll
        for (int mt = 0; mt < 4; mt++)
#pragma unroll
            for (int h = 0; h < 2; h++) {
                const int row = r0 + mt * 16 + h * 8;
                float2* orow = reinterpret_cast<float2*>(Cf + (size_t)row * ldC);
#pragma unroll
                for (int nf = 0; nf < 8; nf++) {
                    const int gc = c0 + nf * 8;
                    orow[gc >> 1] = make_float2(acc[mt][nf][h * 2] + bias[gc],
                                                acc[mt][nf][h * 2 + 1] + bias[gc + 1]);
                }
            }
    } else {   // RELU (opt PERM row scale)
#pragma unroll
        for (int mt = 0; mt < 4; mt++)
#pragma unroll
            for (int h = 0; h < 2; h++) {
                const int row = r0 + mt * 16 + h * 8;
                float s = 1.0f;
                if (PERM) s = sigmoidf_(pa[permrow(row)]);
                uint32_t* oh = reinterpret_cast<uint32_t*>(Ch) + ((size_t)row * 512 >> 1);
#pragma unroll
                for (int nf = 0; nf < 8; nf++) {
                    const int gc = c0 + nf * 8;
                    const float y0 = fmaxf(fmaf(s, acc[mt][nf][h * 2],     bias[gc]),     0.0f);
                    const float y1 = fmaxf(fmaf(s, acc[mt][nf][h * 2 + 1], bias[gc + 1]), 0.0f);
                    __half2 h2;
                    h2.x = __float2half_rn(y0);
                    h2.y = __float2half_rn(y1);
                    oh[gc >> 1] = *reinterpret_cast<uint32_t*>(&h2);
                }
            }
    }
}

// ---------------------------------------------------------------------------
// Fused M + T1 kernel, fp32 A input: 256 thr = 8 warps (2m x 4n), warp tile
// 64x32 per output. A: LDG float4 -> cvt -> STS double-buffered (2 x 16KB);
// B: 3-stage cp.async (3 x 32KB). smem 128KB.
// R17: Hn tile staged into smem (fp16, stride 136 halves, conflict-free)
// after the mainloop — replaces the scattered global Hn gather.
// ---------------------------------------------------------------------------
__global__ void __launch_bounds__(256, 1)
hmma_mf_re(const float* __restrict__ EF,
           const __half* __restrict__ WmE, const __half* __restrict__ W1,
           const float* __restrict__ Hn, const float* __restrict__ bl1,
           __half* __restrict__ Mh, __half* __restrict__ Th)
{
    extern __shared__ __align__(128) uint8_t smem[];
    const uint32_t sA0 = smem_u32(smem);     // 2 x 16KB A slots
    const uint32_t sB0 = sA0 + 32768;        // 3 x 32KB B stages (BM+BT)

    const int tid = threadIdx.x;
    const int wid = tid >> 5, lane = tid & 31;
    const int warp_m = wid & 1, warp_n = wid >> 1;   // 2 x 4
    const int rowBase = blockIdx.y << 7;
    const int colBase = blockIdx.x << 7;

    const int lrow = tid >> 3, lseg = tid & 7;       // 32 rows/sweep
    uint32_t aIdx[4], bOff[4], sOff[4];
#pragma unroll
    for (int i = 0; i < 4; i++) {
        const int row = lrow + i * 32;
        aIdx[i] = ((uint32_t)(rowBase + row) * 512u + lseg * 8) >> 2;  // float4 idx
        bOff[i] = (uint32_t)(colBase + row) * 512u + lseg * 8;
        sOff[i] = swz((uint32_t)row * 128 + lseg * 16);
    }
    const float4* EF4 = reinterpret_cast<const float4*>(EF);

    float4 rA[8];
    auto ldgA = [&](int ch) {
        const uint32_t kq = (uint32_t)(ch * 16);    // 64 halves = 16 float4
#pragma unroll
        for (int i = 0; i < 4; i++) {
            rA[i * 2 + 0] = EF4[aIdx[i] + kq + 0];
            rA[i * 2 + 1] = EF4[aIdx[i] + kq + 1];
        }
    };
    auto stsA = [&](int slot) {
#pragma unroll
        for (int i = 0; i < 4; i++) {
            __half2 p0, p1, p2, p3;
            p0.x = __float2half_rn(rA[i*2].x);   p0.y = __float2half_rn(rA[i*2].y);
            p1.x = __float2half_rn(rA[i*2].z);   p1.y = __float2half_rn(rA[i*2].w);
            p2.x = __float2half_rn(rA[i*2+1].x); p2.y = __float2half_rn(rA[i*2+1].y);
            p3.x = __float2half_rn(rA[i*2+1].z); p3.y = __float2half_rn(rA[i*2+1].w);
            const uint4 v = make_uint4(*reinterpret_cast<uint32_t*>(&p0),
                                       *reinterpret_cast<uint32_t*>(&p1),
                                       *reinterpret_cast<uint32_t*>(&p2),
                                       *reinterpret_cast<uint32_t*>(&p3));
            *reinterpret_cast<uint4*>(smem + slot * 16384 + sOff[i]) = v;
        }
    };
    auto loadB = [&](int st, int ch) {
        const int kb = ch * 64;
        const uint32_t sbM = sB0 + st * 32768;
        const uint32_t sbT = sbM + 16384;
#pragma unroll
        for (int i = 0; i < 4; i++) {
            cp16(sbM + sOff[i], WmE + bOff[i] + kb);
            cp16(sbT + sOff[i], W1  + bOff[i] + kb);
        }
        cp_commit();
    };

    ldgA(0); stsA(0);
    ldgA(1);
    loadB(0, 0); loadB(1, 1);

    float accM[4][4][4], accT[4][4][4];
#pragma unroll
    for (int mt = 0; mt < 4; mt++)
#pragma unroll
        for (int nf = 0; nf < 4; nf++)
#pragma unroll
            for (int j = 0; j < 4; j++) { accM[mt][nf][j] = 0.0f; accT[mt][nf][j] = 0.0f; }

    const int aRow = warp_m * 64 + ((lane >> 3) & 1) * 8 + (lane & 7);
    const uint32_t aK = (uint32_t)(lane >> 4) * 16;
    const int bRow = warp_n * 32 + (lane >> 4) * 8 + (lane & 7);
    const uint32_t bK = (uint32_t)((lane >> 3) & 1) * 16;

#pragma unroll 1
    for (int ch = 0; ch < 8; ch++) {
        if (ch < 7) cp_wait<1>(); else cp_wait<0>();
        __syncthreads();
        if (ch + 1 < 8) stsA((ch + 1) & 1);
        if (ch + 2 < 8) { ldgA(ch + 2); loadB((ch + 2) % 3, ch + 2); }

        const uint32_t sa  = sA0 + (ch & 1) * 16384;
        const uint32_t sbM = sB0 + (ch % 3) * 32768;
        const uint32_t sbT = sbM + 16384;
#pragma unroll
        for (int ks = 0; ks < 4; ks++) {
            uint32_t a[4][4], bM[2][4], bT[2][4];
#pragma unroll
            for (int mt = 0; mt < 4; mt++)
                ldm_x4(a[mt], sa + swz((uint32_t)(aRow + mt * 16) * 128 + ks * 32 + aK));
#pragma unroll
            for (int pr = 0; pr < 2; pr++) {
                const uint32_t off = swz((uint32_t)(bRow + pr * 16) * 128 + ks * 32 + bK);
                ldm_x4(bM[pr], sbM + off);
                ldm_x4(bT[pr], sbT + off);
            }
#pragma unroll
            for (int mt = 0; mt < 4; mt++)
#pragma unroll
                for (int nf = 0; nf < 4; nf++) {
                    mma16816(accM[mt][nf], a[mt],
                             bM[nf >> 1][(nf & 1) * 2], bM[nf >> 1][(nf & 1) * 2 + 1]);
                    mma16816(accT[mt][nf], a[mt],
                             bT[nf >> 1][(nf & 1) * 2], bT[nf >> 1][(nf & 1) * 2 + 1]);
                }
        }
    }

    // ---- stage the Hn tile (64 rows x 128 cols) into smem as fp16 ----
    // Rows of this CTA map to Hn rows (b<<6)|w, b fixed, w = row&63.
    __syncthreads();
    {
        const int b6 = (rowBase >> 12) << 6;
#pragma unroll
        for (int i = 0; i < 8; i++) {
            const int hrow = wid + i * 8;       // 8 warps x 8 sweeps = 64 rows
            const float4 v = *reinterpret_cast<const float4*>(
                Hn + (size_t)(b6 + hrow) * 512 + colBase + lane * 4);
            __half2 pa2, pb2;
            pa2.x = __float2half_rn(v.x); pa2.y = __float2half_rn(v.y);
            pb2.x = __float2half_rn(v.z); pb2.y = __float2half_rn(v.w);
            *reinterpret_cast<uint2*>(smem + (size_t)(hrow * 136 + lane * 4) * 2) =
                make_uint2(*reinterpret_cast<uint32_t*>(&pa2),
                           *reinterpret_cast<uint32_t*>(&pb2));
        }
    }
    __syncthreads();
    const __half* sHn = reinterpret_cast<const __half*>(smem);

    const int r0 = rowBase + warp_m * 64 + (lane >> 2);
    const int c0 = colBase + warp_n * 32 + (lane & 3) * 2;
#pragma unroll
    for (int mt = 0; mt < 4; mt++)
#pragma unroll
        for (int h = 0; h < 2; h++) {
            const int row = r0 + mt * 16 + h * 8;
            const int hbase = (row & 63) * 136 - colBase;
            uint32_t* om = reinterpret_cast<uint32_t*>(Mh) + ((size_t)row * 512 >> 1);
            uint32_t* ot = reinterpret_cast<uint32_t*>(Th) + ((size_t)row * 512 >> 1);
#pragma unroll
            for (int nf = 0; nf < 4; nf++) {
                const int gc = c0 + nf * 8;
                const __half2 hn2 = *reinterpret_cast<const __half2*>(&sHn[hbase + gc]);
                const float m0 = fmaxf(accM[mt][nf][h * 2]     + __half2float(hn2.x), 0.0f);
                const float m1 = fmaxf(accM[mt][nf][h * 2 + 1] + __half2float(hn2.y), 0.0f);
                const float t0 = fmaxf(accT[mt][nf][h * 2]     + bl1[gc],     0.0f);
                const float t1 = fmaxf(accT[mt][nf][h * 2 + 1] + bl1[gc + 1], 0.0f);
                __half2 hm, ht;
                hm.x = __float2half_rn(m0); hm.y = __float2half_rn(m1);
                ht.x = __float2half_rn(t0); ht.y = __float2half_rn(t1);
                om[gc >> 1] = *reinterpret_cast<uint32_t*>(&hm);
                ot[gc >> 1] = *reinterpret_cast<uint32_t*>(&ht);
            }
        }
}

// ---------------------------------------------------------------------------
// Weight conversions (hi-only) + NF cast + pa-accumulator init, one launch.
//   [0,S) Wm edge   [S,2S) Wm node   [2S,3S) Wl1   [3S,4S) Wl2
//   [4S,7S) Wih     [7S,10S) Whh     [10S,12S) NF
//   [12S,12S+16384) pa1/out float4 fill with blo
// ---------------------------------------------------------------------------
__global__ void conv_weights(const float* __restrict__ Wm,
                             const float* __restrict__ Wl1,
                             const float* __restrict__ Wl2,
                             const float* __restrict__ Wih,
                             const float* __restrict__ Whh,
                             const float* __restrict__ NF,
                             __half* __restrict__ Wmh,  __half* __restrict__ WmNh,
                             __half* __restrict__ W1h,  __half* __restrict__ W2h,
                             __half* __restrict__ Wihh, __half* __restrict__ Whhh,
                             __half* __restrict__ NFh,
                             const float* __restrict__ blo,
                             float4* __restrict__ pa1, float4* __restrict__ pa2)
{
    const int idx = blockIdx.x * blockDim.x + threadIdx.x;
    constexpr int S = 512 * 512;
    if (idx >= 12 * S) {
        const int o = idx - 12 * S;
        if (o < Rr / 4) {
            const float v = blo[0];
            const float4 f = make_float4(v, v, v, v);
            pa1[o] = f;
            pa2[o] = f;
        }
        return;
    }
    float x;
    __half* hi;
    int off;
    if (idx < S) {
        off = idx;
        x = Wm[(size_t)(off >> 9) * 1024 + 512 + (off & 511)];
        hi = Wmh + off;
    } else if (idx < 2 * S) {
        off = idx - S;
        x = Wm[(size_t)(off >> 9) * 1024 + (off & 511)];
        hi = WmNh + off;
    } else if (idx < 3 * S) {
        off = idx - 2 * S;
        x = Wl1[off];
        hi = W1h + off;
    } else if (idx < 4 * S) {
        off = idx - 3 * S;
        x = Wl2[off];
        hi = W2h + off;
    } else if (idx < 7 * S) {
        off = idx - 4 * S;
        x = Wih[off];
        hi = Wihh + off;
    } else if (idx < 10 * S) {
        off = idx - 7 * S;
        x = Whh[off];
        hi = Whhh + off;
    } else {
        off = idx - 10 * S;
        x = NF[off];
        hi = NFh + off;
    }
    *hi = __float2half_rn(x);
}

// msum[b,v,:] = sum_w sig(pa2[b,v,w]) * Mh[(b,v,w), :]  -> fp16 hi only
__global__ void msum2(const __half* __restrict__ Mh,
                      const float* __restrict__ pa2,
                      __half* __restrict__ msh)
{
    const int bv = blockIdx.x;
    const int t  = threadIdx.x;   // 128
    __shared__ float sg[64];
    if (t < 64) sg[t] = sigmoidf_(pa2[bv * 64 + t]);
    __syncthreads();
    const uint32_t* mh = reinterpret_cast<const uint32_t*>(Mh + (size_t)bv * 64 * 512);
    const int c = t * 2;
    float a0 = 0.f, a1 = 0.f, a2 = 0.f, a3 = 0.f;
#pragma unroll 4
    for (int w = 0; w < 64; w++) {
        const float s = sg[w];
        const uint32_t h0 = mh[w * 256 + c];
        const uint32_t h1 = mh[w * 256 + c + 1];
        const __half2 H0 = *reinterpret_cast<const __half2*>(&h0);
        const __half2 H1 = *reinterpret_cast<const __half2*>(&h1);
        a0 = fmaf(s, __half2float(H0.x), a0);
        a1 = fmaf(s, __half2float(H0.y), a1);
        a2 = fmaf(s, __half2float(H1.x), a2);
        a3 = fmaf(s, __half2float(H1.y), a3);
    }
    __half2 h2a, h2b;
    h2a.x = __float2half_rn(a0); h2a.y = __float2half_rn(a1);
    h2b.x = __float2half_rn(a2); h2b.y = __float2half_rn(a3);
    uint2* oh = reinterpret_cast<uint2*>(msh + (size_t)bv * 512) + t;
    *oh = make_uint2(*reinterpret_cast<uint32_t*>(&h2a), *reinterpret_cast<uint32_t*>(&h2b));
}

__global__ void gru_readout(const float* __restrict__ GI,
                            const float* __restrict__ GH,
                            const float* __restrict__ NF,
                            const float* __restrict__ Wr1, const float* __restrict__ br1,
                            const float* __restrict__ Wr2, const float* __restrict__ br2,
                            float* __restrict__ out)
{
    const int row = blockIdx.x;
    __shared__ float hn[512];
    const int t = threadIdx.x;   // 256
    const float* gi = GI + (size_t)row * 1536;
    const float* gh = GH + (size_t)row * 1536;
    const float* h  = NF + (size_t)row * 512;
    for (int d = t; d < 512; d += 256) {
        const float r = sigmoidf_(gi[d] + gh[d]);
        const float z = sigmoidf_(gi[512 + d] + gh[512 + d]);
        const float n = tanhf(gi[1024 + d] + r * gh[1024 + d]);
        hn[d] = (1.0f - z) * n + z * h[d];
    }
    __syncthreads();
    const int warp = t >> 5, lane = t & 31;
    for (int o = warp; o < 28; o += 8) {
        const float* Wr = (o < 26) ? (Wr1 + o * 512) : (Wr2 + (o - 26) * 512);
        float acc = 0.0f;
        for (int k = lane; k < 512; k += 32) acc = fmaf(hn[k], Wr[k], acc);
#pragma unroll
        for (int off = 16; off; off >>= 1)
            acc += __shfl_down_sync(0xffffffffu, acc, off);
        if (lane == 0) {
            if (o < 26) out[65536 + row * 26 + o]               = acc + br1[o];
            else        out[65536 + 26624 + row * 2 + (o - 26)] = acc + br2[o - 26];
        }
    }
}

} // namespace

extern "C" void kernel_launch(void* const* d_in, const int* /*in_sizes*/, int /*n_in*/,
                              void* d_out, int /*out_size*/)
{
    const float* EF  = (const float*)d_in[0];
    const float* NF  = (const float*)d_in[1];
    const float* Wm  = (const float*)d_in[4];
    const float* bm  = (const float*)d_in[5];
    const float* Wl1 = (const float*)d_in[6];
    const float* bl1 = (const float*)d_in[7];
    const float* Wl2 = (const float*)d_in[8];
    const float* bl2 = (const float*)d_in[9];
    const float* Wlo = (const float*)d_in[10];
    const float* blo = (const float*)d_in[11];
    const float* Wih = (const float*)d_in[12];
    const float* bih = (const float*)d_in[13];
    const float* Whh = (const float*)d_in[14];
    const float* bhh = (const float*)d_in[15];
    const float* Wr1 = (const float*)d_in[16];
    const float* br1 = (const float*)d_in[17];
    const float* Wr2 = (const float*)d_in[18];
    const float* br2 = (const float*)d_in[19];
    float* out = (float*)d_out;

    __half *pMh, *pTh;
    __half *pWmh, *pWmNh, *pW1h, *pW2h;
    __half *pWihh, *pWhhh, *pNFh, *pmsh;
    float *pHn, *pPa1, *pGI, *pGH;
    cudaGetSymbolAddress((void**)&pMh,   g_Mh);
    cudaGetSymbolAddress((void**)&pTh,   g_Th);
    cudaGetSymbolAddress((void**)&pWmh,  g_Wmh);
    cudaGetSymbolAddress((void**)&pWmNh, g_WmNh);
    cudaGetSymbolAddress((void**)&pW1h,  g_W1h);
    cudaGetSymbolAddress((void**)&pW2h,  g_W2h);
    cudaGetSymbolAddress((void**)&pWihh, g_Wihh);
    cudaGetSymbolAddress((void**)&pWhhh, g_Whhh);
    cudaGetSymbolAddress((void**)&pNFh,  g_NFh);
    cudaGetSymbolAddress((void**)&pmsh,  g_msh);
    cudaGetSymbolAddress((void**)&pHn,   g_Hn);
    cudaGetSymbolAddress((void**)&pPa1,  g_pa1);
    cudaGetSymbolAddress((void**)&pGI,   g_GI);
    cudaGetSymbolAddress((void**)&pGH,   g_GH);

    auto kBIAS1 = hmma_gemm<TEPI_BIAS, false, 1>;   // Hn, GI, GH (1-plane)
    auto kRP    = hmma_gemm<TEPI_RELU, true,  1>;
    auto kDOT   = hmma_gemm<TEPI_DOT,  false, 1>;
    cudaFuncSetAttribute(kBIAS1, cudaFuncAttributeMaxDynamicSharedMemorySize, SMEM_BYTES);
    cudaFuncSetAttribute(kRP,    cudaFuncAttributeMaxDynamicSharedMemorySize, SMEM_BYTES);
    cudaFuncSetAttribute(kDOT,   cudaFuncAttributeMaxDynamicSharedMemorySize, SMEM_BYTES);
    cudaFuncSetAttribute(hmma_mf_re, cudaFuncAttributeMaxDynamicSharedMemorySize, 131072);

    // all conversions + NF cast + pa init in one launch
    conv_weights<<<12352, 256>>>(Wm, Wl1, Wl2, Wih, Whh, NF,
                                 pWmh, pWmNh, pW1h, pW2h,
                                 pWihh, pWhhh, pNFh,
                                 blo, (float4*)pPa1, (float4*)out);

    // Hn = NF @ Wm[:, :512]^T + bm   (1-plane; feeds fp16-rounded M)
    kBIAS1<<<dim3(4, 8, 1), 128, SMEM_BYTES>>>(pNFh, nullptr, pWmNh, nullptr, bm,
                                               nullptr, nullptr, nullptr,
                                               pHn, 512, nullptr,
                                               nullptr, nullptr, nullptr, nullptr,
                                               nullptr, nullptr);

    // M + T1 in one fused pass, consuming fp32 EF directly (smem-staged Hn)
    hmma_mf_re<<<dim3(4, 512), 256, 131072>>>(EF, pWmh, pW1h, pHn, bl1, pMh, pTh);

    const dim3 gTC(4, 512, 1);
    // pa1 += dot(relu(T1 @ Wl2^T + bl2), Wlo)
    kDOT<<<gTC, 128, SMEM_BYTES>>>(pTh, nullptr, pW2h, nullptr, bl2, Wlo,
                                   nullptr, nullptr, nullptr, 0, pPa1,
                                   nullptr, nullptr, nullptr, nullptr,
                                   nullptr, nullptr);
    // T1' = relu(sig(pa1[perm]) * M[perm] @ Wl1^T + bl1) -> Th
    kRP<<<gTC, 128, SMEM_BYTES>>>(pMh, nullptr, pW1h, nullptr, bl1, nullptr,
                                  pPa1, pTh, nullptr, 0, nullptr,
                                  nullptr, nullptr, nullptr, nullptr,
                                  nullptr, nullptr);
    // pred_adj += dot(relu(T1' @ Wl2^T + bl2), Wlo)
    kDOT<<<gTC, 128, SMEM_BYTES>>>(pTh, nullptr, pW2h, nullptr, bl2, Wlo,
                                   nullptr, nullptr, nullptr, 0, out,
                                   nullptr, nullptr, nullptr, nullptr,
                                   nullptr, nullptr);

    msum2<<<Bb * Nn, 128>>>(pMh, out, pmsh);
    // GI and GH in one dual launch (1-plane: Ah*Bh)
    kBIAS1<<<dim3(12, 8, 2), 128, SMEM_BYTES>>>(pmsh, nullptr, pWihh, nullptr, bih,
                                                nullptr, nullptr, nullptr,
                                                pGI, 1536, nullptr,
                                                pNFh, nullptr, pWhhh, nullptr,
                                                bhh, pGH);
    gru_readout<<<Bb * Nn, 256>>>(pGI, pGH, NF, Wr1, br1, Wr2, br2, out);
}